// round 1
// baseline (speedup 1.0000x reference)
#include <cuda_runtime.h>
#include <math.h>

#define BATCH 2
#define SEQ   2048
#define DM    768
#define NS    64
#define MROWS (BATCH*SEQ)   // 4096

// Scratch (device globals; no allocation allowed in kernel_launch)
__device__ float g_xn[MROWS*DM];   // layernorm output
__device__ float g_u [MROWS*DM];   // in_proj output
__device__ float g_ys[MROWS*DM];   // scan output

// ---------------------------------------------------------------------------
// LayerNorm: one block per row of 768
// ---------------------------------------------------------------------------
__global__ void ln_kernel(const float* __restrict__ x,
                          const float* __restrict__ gamma,
                          const float* __restrict__ beta,
                          float* __restrict__ out) {
    int row = blockIdx.x;
    const float* xr = x + (size_t)row * DM;
    float s = 0.f, s2 = 0.f;
    for (int i = threadIdx.x; i < DM; i += blockDim.x) {
        float v = xr[i];
        s += v; s2 += v * v;
    }
    __shared__ float sh1[32], sh2[32];
    int lane = threadIdx.x & 31, wid = threadIdx.x >> 5;
    #pragma unroll
    for (int o = 16; o; o >>= 1) {
        s  += __shfl_xor_sync(0xffffffffu, s,  o);
        s2 += __shfl_xor_sync(0xffffffffu, s2, o);
    }
    if (lane == 0) { sh1[wid] = s; sh2[wid] = s2; }
    __syncthreads();
    int nw = blockDim.x >> 5;
    if (wid == 0) {
        s  = (lane < nw) ? sh1[lane] : 0.f;
        s2 = (lane < nw) ? sh2[lane] : 0.f;
        #pragma unroll
        for (int o = 16; o; o >>= 1) {
            s  += __shfl_xor_sync(0xffffffffu, s,  o);
            s2 += __shfl_xor_sync(0xffffffffu, s2, o);
        }
        if (lane == 0) { sh1[0] = s; sh2[0] = s2; }
    }
    __syncthreads();
    float mu  = sh1[0] * (1.0f / DM);
    float var = sh2[0] * (1.0f / DM) - mu * mu;
    float inv = rsqrtf(var + 1e-5f);
    float* orow = out + (size_t)row * DM;
    for (int i = threadIdx.x; i < DM; i += blockDim.x)
        orow[i] = (xr[i] - mu) * inv * gamma[i] + beta[i];
}

// ---------------------------------------------------------------------------
// GEMM: C[M,N] = A[M,K] @ W[N,K]^T + bias[N] (+ res[M,N])
// M=4096, N=768, K=768. BM=BN=64, BK=16, 256 threads, 4x4 microtile.
// ---------------------------------------------------------------------------
template<bool ADD_RES>
__global__ void gemm_nt_kernel(const float* __restrict__ A,
                               const float* __restrict__ W,
                               const float* __restrict__ bias,
                               const float* __restrict__ res,
                               float* __restrict__ C) {
    const int BM = 64, BN = 64, BK = 16;
    __shared__ float As[BK][BM];
    __shared__ float Ws[BK][BN];
    int m0 = blockIdx.y * BM, n0 = blockIdx.x * BN;
    int tid = threadIdx.x;               // 0..255
    int tx = tid & 15, ty = tid >> 4;    // 16x16
    float acc[4][4] = {};
    for (int k0 = 0; k0 < DM; k0 += BK) {
        #pragma unroll
        for (int i = 0; i < 4; i++) {
            int idx = tid + i * 256;     // 0..1023
            int k = idx & 15, m = idx >> 4;
            As[k][m] = A[(size_t)(m0 + m) * DM + k0 + k];
            Ws[k][m] = W[(size_t)(n0 + m) * DM + k0 + k];
        }
        __syncthreads();
        #pragma unroll
        for (int k = 0; k < BK; k++) {
            float ra[4], rb[4];
            #pragma unroll
            for (int i = 0; i < 4; i++) ra[i] = As[k][ty * 4 + i];
            #pragma unroll
            for (int j = 0; j < 4; j++) rb[j] = Ws[k][tx * 4 + j];
            #pragma unroll
            for (int i = 0; i < 4; i++)
                #pragma unroll
                for (int j = 0; j < 4; j++)
                    acc[i][j] = fmaf(ra[i], rb[j], acc[i][j]);
        }
        __syncthreads();
    }
    #pragma unroll
    for (int i = 0; i < 4; i++) {
        int m = m0 + ty * 4 + i;
        #pragma unroll
        for (int j = 0; j < 4; j++) {
            int n = n0 + tx * 4 + j;
            float v = acc[i][j] + bias[n];
            if (ADD_RES) v += res[(size_t)m * DM + n];
            C[(size_t)m * DM + n] = v;
        }
    }
}

// ---------------------------------------------------------------------------
// SSM scan: one warp per (b,d) channel, 2 states per lane.
// h = A_bar*h + B_bar*u;  y = sum_n C*h + D*u
// ---------------------------------------------------------------------------
__global__ void scan_kernel(const float* __restrict__ u,
                            const float* __restrict__ log_A,
                            const float* __restrict__ B_p,
                            const float* __restrict__ C_p,
                            const float* __restrict__ D_p,
                            const float* __restrict__ log_dt,
                            float* __restrict__ yout) {
    int warp = (blockIdx.x * blockDim.x + threadIdx.x) >> 5;
    int lane = threadIdx.x & 31;
    if (warp >= BATCH * DM) return;
    int b = warp / DM;
    int d = warp % DM;
    int n0 = lane * 2;

    float dt = expf(log_dt[d]);
    float la0 = log_A[d * NS + n0];
    float la1 = log_A[d * NS + n0 + 1];
    float Ab0 = expf(dt * (-expf(la0)));
    float Ab1 = expf(dt * (-expf(la1)));
    float Bb0 = B_p[d * NS + n0]     * dt;
    float Bb1 = B_p[d * NS + n0 + 1] * dt;
    float C0  = C_p[d * NS + n0];
    float C1  = C_p[d * NS + n0 + 1];
    float Dd  = D_p[d];

    const float* up = u    + (size_t)b * SEQ * DM + d;
    float*       yp = yout + (size_t)b * SEQ * DM + d;

    float h0 = 0.f, h1 = 0.f;
    for (int t = 0; t < SEQ; t++) {
        float ut = __ldg(up + (size_t)t * DM);
        h0 = fmaf(Ab0, h0, Bb0 * ut);
        h1 = fmaf(Ab1, h1, Bb1 * ut);
        float p = fmaf(C0, h0, C1 * h1);
        #pragma unroll
        for (int o = 16; o; o >>= 1)
            p += __shfl_xor_sync(0xffffffffu, p, o);
        if (lane == 0)
            yp[(size_t)t * DM] = fmaf(Dd, ut, p);
    }
}

// ---------------------------------------------------------------------------
extern "C" void kernel_launch(void* const* d_in, const int* in_sizes, int n_in,
                              void* d_out, int out_size) {
    const float* x        = (const float*)d_in[0];
    const float* ln_gamma = (const float*)d_in[1];
    const float* ln_beta  = (const float*)d_in[2];
    const float* W_in     = (const float*)d_in[3];
    const float* b_in     = (const float*)d_in[4];
    const float* log_A    = (const float*)d_in[5];
    const float* B_p      = (const float*)d_in[6];
    const float* C_p      = (const float*)d_in[7];
    const float* D_p      = (const float*)d_in[8];
    const float* log_dt   = (const float*)d_in[9];
    const float* W_out    = (const float*)d_in[10];
    const float* b_out    = (const float*)d_in[11];
    float* out = (float*)d_out;

    float *xn, *u, *ys;
    cudaGetSymbolAddress((void**)&xn, g_xn);
    cudaGetSymbolAddress((void**)&u,  g_u);
    cudaGetSymbolAddress((void**)&ys, g_ys);

    // 1) LayerNorm
    ln_kernel<<<MROWS, 256>>>(x, ln_gamma, ln_beta, xn);

    // 2) u = xn @ W_in^T + b_in
    dim3 g1(DM / 64, MROWS / 64);
    gemm_nt_kernel<false><<<g1, 256>>>(xn, W_in, b_in, nullptr, u);

    // 3) SSM scan
    scan_kernel<<<(BATCH * DM * 32) / 128, 128>>>(u, log_A, B_p, C_p, D_p, log_dt, ys);

    // 4) out = ys @ W_out^T + b_out + x
    gemm_nt_kernel<true><<<g1, 256>>>(ys, W_out, b_out, x, out);
}

// round 2
// speedup vs baseline: 2.2365x; 2.2365x over previous
#include <cuda_runtime.h>
#include <math.h>

#define BATCH 2
#define SEQ   2048
#define DM    768
#define NS    64
#define MROWS (BATCH*SEQ)   // 4096

// Scratch (device globals)
__device__ float g_xn [MROWS*DM];   // layernorm output  [m][d]
__device__ float g_u  [MROWS*DM];   // in_proj output    [m][d]
__device__ float g_ysT[DM*MROWS];   // scan output, transposed [d][m]

// ---------------------------------------------------------------------------
// LayerNorm: one warp per row (768 floats = 192 float4 = 6 per lane)
// ---------------------------------------------------------------------------
__global__ void ln_kernel(const float* __restrict__ x,
                          const float* __restrict__ gamma,
                          const float* __restrict__ beta,
                          float* __restrict__ out) {
    int w = threadIdx.x >> 5, lane = threadIdx.x & 31;
    int row = blockIdx.x * 8 + w;
    const float4* xr = (const float4*)(x + (size_t)row * DM);
    float4 v[6];
    float s = 0.f, s2 = 0.f;
    #pragma unroll
    for (int i = 0; i < 6; i++) {
        v[i] = xr[lane + 32 * i];
        s  += v[i].x + v[i].y + v[i].z + v[i].w;
        s2 += v[i].x*v[i].x + v[i].y*v[i].y + v[i].z*v[i].z + v[i].w*v[i].w;
    }
    #pragma unroll
    for (int o = 16; o; o >>= 1) {
        s  += __shfl_xor_sync(0xffffffffu, s,  o);
        s2 += __shfl_xor_sync(0xffffffffu, s2, o);
    }
    float mu  = s * (1.0f / DM);
    float var = s2 * (1.0f / DM) - mu * mu;
    float inv = rsqrtf(var + 1e-5f);
    const float4* g4 = (const float4*)gamma;
    const float4* b4 = (const float4*)beta;
    float4* orow = (float4*)(out + (size_t)row * DM);
    #pragma unroll
    for (int i = 0; i < 6; i++) {
        float4 g = g4[lane + 32 * i], b = b4[lane + 32 * i], o;
        o.x = (v[i].x - mu) * inv * g.x + b.x;
        o.y = (v[i].y - mu) * inv * g.y + b.y;
        o.z = (v[i].z - mu) * inv * g.z + b.z;
        o.w = (v[i].w - mu) * inv * g.w + b.w;
        orow[lane + 32 * i] = o;
    }
}

// ---------------------------------------------------------------------------
// GEMM (normal A): C[M,N] = A[M,K] @ W[N,K]^T + bias  (A row-major)
// BM=128, BN=64, BK=16, 256 threads, 8x4 microtile, float4 everywhere.
// ---------------------------------------------------------------------------
__global__ __launch_bounds__(256, 3)
void gemm_nt(const float* __restrict__ A, const float* __restrict__ W,
             const float* __restrict__ bias, float* __restrict__ C) {
    const int BK = 16, NT = DM / BK;
    __shared__ float As[BK][132];   // pad->2-way max conflict on transpose STS
    __shared__ float Ws[BK][68];
    int m0 = blockIdx.y * 128, n0 = blockIdx.x * 64;
    int tid = threadIdx.x, tx = tid & 15, ty = tid >> 4;
    int am = tid >> 2, ak = (tid & 3) * 4;   // am:0..63, ak:{0,4,8,12}
    const float* Ap0 = A + (size_t)(m0 + am) * DM + ak;
    const float* Ap1 = Ap0 + (size_t)64 * DM;
    const float* Wp  = W + (size_t)(n0 + am) * DM + ak;

    float4 a0 = *(const float4*)Ap0;
    float4 a1 = *(const float4*)Ap1;
    float4 w0 = *(const float4*)Wp;
    As[ak+0][am] = a0.x; As[ak+1][am] = a0.y; As[ak+2][am] = a0.z; As[ak+3][am] = a0.w;
    As[ak+0][am+64] = a1.x; As[ak+1][am+64] = a1.y; As[ak+2][am+64] = a1.z; As[ak+3][am+64] = a1.w;
    Ws[ak+0][am] = w0.x; Ws[ak+1][am] = w0.y; Ws[ak+2][am] = w0.z; Ws[ak+3][am] = w0.w;
    __syncthreads();

    float acc[8][4] = {};
    for (int kt = 0; kt < NT; kt++) {
        float4 na0, na1, nw0;
        if (kt + 1 < NT) {
            int off = (kt + 1) * BK;
            na0 = *(const float4*)(Ap0 + off);
            na1 = *(const float4*)(Ap1 + off);
            nw0 = *(const float4*)(Wp  + off);
        }
        #pragma unroll
        for (int k = 0; k < BK; k++) {
            float4 ra0 = *(const float4*)&As[k][ty * 8];
            float4 ra1 = *(const float4*)&As[k][ty * 8 + 4];
            float4 rb  = *(const float4*)&Ws[k][tx * 4];
            float ra[8] = {ra0.x, ra0.y, ra0.z, ra0.w, ra1.x, ra1.y, ra1.z, ra1.w};
            float rv[4] = {rb.x, rb.y, rb.z, rb.w};
            #pragma unroll
            for (int i = 0; i < 8; i++)
                #pragma unroll
                for (int j = 0; j < 4; j++)
                    acc[i][j] = fmaf(ra[i], rv[j], acc[i][j]);
        }
        if (kt + 1 < NT) {
            __syncthreads();
            As[ak+0][am] = na0.x; As[ak+1][am] = na0.y; As[ak+2][am] = na0.z; As[ak+3][am] = na0.w;
            As[ak+0][am+64] = na1.x; As[ak+1][am+64] = na1.y; As[ak+2][am+64] = na1.z; As[ak+3][am+64] = na1.w;
            Ws[ak+0][am] = nw0.x; Ws[ak+1][am] = nw0.y; Ws[ak+2][am] = nw0.z; Ws[ak+3][am] = nw0.w;
            __syncthreads();
        }
    }
    float4 bb = *(const float4*)(bias + n0 + tx * 4);
    #pragma unroll
    for (int i = 0; i < 8; i++) {
        int m = m0 + ty * 8 + i;
        float4 o;
        o.x = acc[i][0] + bb.x; o.y = acc[i][1] + bb.y;
        o.z = acc[i][2] + bb.z; o.w = acc[i][3] + bb.w;
        *(float4*)(C + (size_t)m * DM + n0 + tx * 4) = o;
    }
}

// ---------------------------------------------------------------------------
// GEMM (transposed A): C[M,N] = AT^T[M,K] @ W[N,K]^T + bias + res
// AT is [K=DM][M=MROWS] row-major -> contiguous m per k row, direct STS.128.
// ---------------------------------------------------------------------------
__global__ __launch_bounds__(256, 3)
void gemm_tn_res(const float* __restrict__ AT, const float* __restrict__ W,
                 const float* __restrict__ bias, const float* __restrict__ res,
                 float* __restrict__ C) {
    const int BK = 16, NT = DM / BK;
    __shared__ float As[BK][128];
    __shared__ float Ws[BK][68];
    int m0 = blockIdx.y * 128, n0 = blockIdx.x * 64;
    int tid = threadIdx.x, tx = tid & 15, ty = tid >> 4;
    int ak2 = tid >> 5;            // 0..7
    int am2 = (tid & 31) * 4;      // 0..124
    int am = tid >> 2, ak = (tid & 3) * 4;
    const float* Atp0 = AT + (size_t)ak2 * MROWS + m0 + am2;
    const float* Atp1 = Atp0 + (size_t)8 * MROWS;
    const float* Wp   = W + (size_t)(n0 + am) * DM + ak;

    float4 a0 = *(const float4*)Atp0;
    float4 a1 = *(const float4*)Atp1;
    float4 w0 = *(const float4*)Wp;
    *(float4*)&As[ak2][am2]     = a0;
    *(float4*)&As[ak2 + 8][am2] = a1;
    Ws[ak+0][am] = w0.x; Ws[ak+1][am] = w0.y; Ws[ak+2][am] = w0.z; Ws[ak+3][am] = w0.w;
    __syncthreads();

    float acc[8][4] = {};
    for (int kt = 0; kt < NT; kt++) {
        float4 na0, na1, nw0;
        if (kt + 1 < NT) {
            size_t offA = (size_t)(kt + 1) * BK * MROWS;
            na0 = *(const float4*)(Atp0 + offA);
            na1 = *(const float4*)(Atp1 + offA);
            nw0 = *(const float4*)(Wp + (kt + 1) * BK);
        }
        #pragma unroll
        for (int k = 0; k < BK; k++) {
            float4 ra0 = *(const float4*)&As[k][ty * 8];
            float4 ra1 = *(const float4*)&As[k][ty * 8 + 4];
            float4 rb  = *(const float4*)&Ws[k][tx * 4];
            float ra[8] = {ra0.x, ra0.y, ra0.z, ra0.w, ra1.x, ra1.y, ra1.z, ra1.w};
            float rv[4] = {rb.x, rb.y, rb.z, rb.w};
            #pragma unroll
            for (int i = 0; i < 8; i++)
                #pragma unroll
                for (int j = 0; j < 4; j++)
                    acc[i][j] = fmaf(ra[i], rv[j], acc[i][j]);
        }
        if (kt + 1 < NT) {
            __syncthreads();
            *(float4*)&As[ak2][am2]     = na0;
            *(float4*)&As[ak2 + 8][am2] = na1;
            Ws[ak+0][am] = nw0.x; Ws[ak+1][am] = nw0.y; Ws[ak+2][am] = nw0.z; Ws[ak+3][am] = nw0.w;
            __syncthreads();
        }
    }
    float4 bb = *(const float4*)(bias + n0 + tx * 4);
    #pragma unroll
    for (int i = 0; i < 8; i++) {
        int m = m0 + ty * 8 + i;
        float4 r = *(const float4*)(res + (size_t)m * DM + n0 + tx * 4);
        float4 o;
        o.x = acc[i][0] + bb.x + r.x; o.y = acc[i][1] + bb.y + r.y;
        o.z = acc[i][2] + bb.z + r.z; o.w = acc[i][3] + bb.w + r.w;
        *(float4*)(C + (size_t)m * DM + n0 + tx * 4) = o;
    }
}

// ---------------------------------------------------------------------------
// SSM scan: one warp per (b,d), 2 states/lane, 8-timestep shuffle batches.
// Writes transposed output ysT[d][b*SEQ + t] (coalesced per warp).
// ---------------------------------------------------------------------------
__global__ void scan_kernel(const float* __restrict__ u,
                            const float* __restrict__ log_A,
                            const float* __restrict__ B_p,
                            const float* __restrict__ C_p,
                            const float* __restrict__ D_p,
                            const float* __restrict__ log_dt,
                            float* __restrict__ ysT) {
    int warp = (blockIdx.x * blockDim.x + threadIdx.x) >> 5;
    int lane = threadIdx.x & 31;
    if (warp >= BATCH * DM) return;
    int b = warp / DM, d = warp % DM;
    int n0 = lane * 2;

    float dt  = expf(log_dt[d]);
    float Ab0 = expf(dt * (-expf(log_A[d * NS + n0])));
    float Ab1 = expf(dt * (-expf(log_A[d * NS + n0 + 1])));
    float Bb0 = B_p[d * NS + n0]     * dt;
    float Bb1 = B_p[d * NS + n0 + 1] * dt;
    float C0  = C_p[d * NS + n0];
    float C1  = C_p[d * NS + n0 + 1];
    float Dd  = D_p[d];

    const float* up = u + (size_t)b * SEQ * DM + d;
    float* yp = ysT + (size_t)d * MROWS + (size_t)b * SEQ;

    float h0 = 0.f, h1 = 0.f;
    for (int t0 = 0; t0 < SEQ; t0 += 8) {
        float p[8], uu[8];
        #pragma unroll
        for (int i = 0; i < 8; i++) {
            float ut = __ldg(up + (size_t)(t0 + i) * DM);
            uu[i] = ut;
            h0 = fmaf(Ab0, h0, Bb0 * ut);
            h1 = fmaf(Ab1, h1, Bb1 * ut);
            p[i] = fmaf(C0, h0, C1 * h1);
        }
        #pragma unroll
        for (int o = 16; o; o >>= 1)
            #pragma unroll
            for (int i = 0; i < 8; i++)
                p[i] += __shfl_xor_sync(0xffffffffu, p[i], o);
        if (lane == 0) {
            #pragma unroll
            for (int i = 0; i < 8; i++)
                yp[t0 + i] = fmaf(Dd, uu[i], p[i]);
        }
    }
}

// ---------------------------------------------------------------------------
extern "C" void kernel_launch(void* const* d_in, const int* in_sizes, int n_in,
                              void* d_out, int out_size) {
    const float* x        = (const float*)d_in[0];
    const float* ln_gamma = (const float*)d_in[1];
    const float* ln_beta  = (const float*)d_in[2];
    const float* W_in     = (const float*)d_in[3];
    const float* b_in     = (const float*)d_in[4];
    const float* log_A    = (const float*)d_in[5];
    const float* B_p      = (const float*)d_in[6];
    const float* C_p      = (const float*)d_in[7];
    const float* D_p      = (const float*)d_in[8];
    const float* log_dt   = (const float*)d_in[9];
    const float* W_out    = (const float*)d_in[10];
    const float* b_out    = (const float*)d_in[11];
    float* out = (float*)d_out;

    float *xn, *u, *ysT;
    cudaGetSymbolAddress((void**)&xn,  g_xn);
    cudaGetSymbolAddress((void**)&u,   g_u);
    cudaGetSymbolAddress((void**)&ysT, g_ysT);

    ln_kernel<<<MROWS / 8, 256>>>(x, ln_gamma, ln_beta, xn);

    dim3 g1(DM / 64, MROWS / 128);
    gemm_nt<<<g1, 256>>>(xn, W_in, b_in, u);

    scan_kernel<<<(BATCH * DM * 32) / 128, 128>>>(u, log_A, B_p, C_p, D_p, log_dt, ysT);

    gemm_tn_res<<<g1, 256>>>(ysT, W_out, b_out, x, out);
}

// round 4
// speedup vs baseline: 3.4608x; 1.5474x over previous
#include <cuda_runtime.h>
#include <cstdint>
#include <math.h>

#define BATCH 2
#define SEQ   2048
#define DM    768
#define NS    64
#define MROWS (BATCH*SEQ)   // 4096

// Scratch (device globals)
__device__ float g_xn [MROWS*DM];   // layernorm output  [m][d]
__device__ float g_u  [MROWS*DM];   // in_proj output    [m][d]
__device__ float g_ysT[DM*MROWS];   // scan output, transposed [d][m]

__device__ __forceinline__ float4 tf32x4(float4 v) {
    float4 r;
    asm("cvt.rna.tf32.f32 %0, %1;" : "=f"(r.x) : "f"(v.x));
    asm("cvt.rna.tf32.f32 %0, %1;" : "=f"(r.y) : "f"(v.y));
    asm("cvt.rna.tf32.f32 %0, %1;" : "=f"(r.z) : "f"(v.z));
    asm("cvt.rna.tf32.f32 %0, %1;" : "=f"(r.w) : "f"(v.w));
    return r;
}

// ---------------------------------------------------------------------------
// LayerNorm: one warp per row
// ---------------------------------------------------------------------------
__global__ void ln_kernel(const float* __restrict__ x,
                          const float* __restrict__ gamma,
                          const float* __restrict__ beta,
                          float* __restrict__ out) {
    int w = threadIdx.x >> 5, lane = threadIdx.x & 31;
    int row = blockIdx.x * 8 + w;
    const float4* xr = (const float4*)(x + (size_t)row * DM);
    float4 v[6];
    float s = 0.f, s2 = 0.f;
    #pragma unroll
    for (int i = 0; i < 6; i++) {
        v[i] = xr[lane + 32 * i];
        s  += v[i].x + v[i].y + v[i].z + v[i].w;
        s2 += v[i].x*v[i].x + v[i].y*v[i].y + v[i].z*v[i].z + v[i].w*v[i].w;
    }
    #pragma unroll
    for (int o = 16; o; o >>= 1) {
        s  += __shfl_xor_sync(0xffffffffu, s,  o);
        s2 += __shfl_xor_sync(0xffffffffu, s2, o);
    }
    float mu  = s * (1.0f / DM);
    float var = s2 * (1.0f / DM) - mu * mu;
    float inv = rsqrtf(var + 1e-5f);
    const float4* g4 = (const float4*)gamma;
    const float4* b4 = (const float4*)beta;
    float4* orow = (float4*)(out + (size_t)row * DM);
    #pragma unroll
    for (int i = 0; i < 6; i++) {
        float4 g = g4[lane + 32 * i], b = b4[lane + 32 * i], o;
        o.x = (v[i].x - mu) * inv * g.x + b.x;
        o.y = (v[i].y - mu) * inv * g.y + b.y;
        o.z = (v[i].z - mu) * inv * g.z + b.z;
        o.w = (v[i].w - mu) * inv * g.w + b.w;
        orow[lane + 32 * i] = o;
    }
}

// ---------------------------------------------------------------------------
// tf32 mma.sync GEMM: C[M,N] = A @ W^T + bias (+res)
// A_TRANS=false: A row-major [M][K].  A_TRANS=true: A is AT[K][M].
// Block 128x128, BK=16, 8 warps (2m x 4n), warp tile 64x32, m16n8k8 frags.
// Smem: A pad-20 (or Ak pad-136), B pad-20 -> conflict-free fragment LDS.
// ---------------------------------------------------------------------------
template<bool A_TRANS, bool ADD_RES>
__global__ __launch_bounds__(256, 2)
void gemm_mma(const float* __restrict__ A, const float* __restrict__ W,
              const float* __restrict__ bias, const float* __restrict__ res,
              float* __restrict__ C) {
    constexpr int AS_FLOATS = A_TRANS ? (16 * 136) : (128 * 20);
    __shared__ float As[2][AS_FLOATS];
    __shared__ float Bs[2][128 * 20];

    const int tid = threadIdx.x;
    const int w = tid >> 5, lane = tid & 31;
    const int wm = (w & 1) * 64, wn = (w >> 1) * 32;
    const int g = lane >> 2, t = lane & 3;
    const int m0 = blockIdx.y * 128, n0 = blockIdx.x * 128;

    float4 pa[2], pw[2];

    auto gload = [&](int kt) {
        #pragma unroll
        for (int j = 0; j < 2; j++) {
            int f4 = tid + j * 256;
            if (A_TRANS) {
                int r = f4 >> 5, c = f4 & 31;
                pa[j] = *(const float4*)(A + (size_t)(kt * 16 + r) * MROWS + m0 + c * 4);
            } else {
                int r = f4 >> 2, c4 = f4 & 3;
                pa[j] = *(const float4*)(A + (size_t)(m0 + r) * DM + kt * 16 + c4 * 4);
            }
            int r = f4 >> 2, c4 = f4 & 3;
            pw[j] = *(const float4*)(W + (size_t)(n0 + r) * DM + kt * 16 + c4 * 4);
        }
    };
    auto sstore = [&](int s) {
        #pragma unroll
        for (int j = 0; j < 2; j++) {
            int f4 = tid + j * 256;
            float4 ta = tf32x4(pa[j]), tw = tf32x4(pw[j]);
            if (A_TRANS) {
                int r = f4 >> 5, c = f4 & 31;
                *(float4*)&As[s][r * 136 + c * 4] = ta;
            } else {
                int r = f4 >> 2, c4 = f4 & 3;
                *(float4*)&As[s][r * 20 + c4 * 4] = ta;
            }
            int r = f4 >> 2, c4 = f4 & 3;
            *(float4*)&Bs[s][r * 20 + c4 * 4] = tw;
        }
    };

    float acc[4][4][4] = {};

    gload(0);
    sstore(0);
    __syncthreads();

    const int NKT = DM / 16;   // 48
    for (int kt = 0; kt < NKT; kt++) {
        int s = kt & 1;
        if (kt + 1 < NKT) gload(kt + 1);
        #pragma unroll
        for (int ks = 0; ks < 2; ks++) {
            uint32_t af[4][4], bf[4][2];
            #pragma unroll
            for (int mt = 0; mt < 4; mt++) {
                int m = wm + mt * 16;
                if (A_TRANS) {
                    af[mt][0] = __float_as_uint(As[s][(ks*8 + t)     * 136 + m + g]);
                    af[mt][1] = __float_as_uint(As[s][(ks*8 + t)     * 136 + m + g + 8]);
                    af[mt][2] = __float_as_uint(As[s][(ks*8 + t + 4) * 136 + m + g]);
                    af[mt][3] = __float_as_uint(As[s][(ks*8 + t + 4) * 136 + m + g + 8]);
                } else {
                    af[mt][0] = __float_as_uint(As[s][(m + g)     * 20 + ks*8 + t]);
                    af[mt][1] = __float_as_uint(As[s][(m + g + 8) * 20 + ks*8 + t]);
                    af[mt][2] = __float_as_uint(As[s][(m + g)     * 20 + ks*8 + t + 4]);
                    af[mt][3] = __float_as_uint(As[s][(m + g + 8) * 20 + ks*8 + t + 4]);
                }
            }
            #pragma unroll
            for (int nt = 0; nt < 4; nt++) {
                int n = wn + nt * 8;
                bf[nt][0] = __float_as_uint(Bs[s][(n + g) * 20 + ks*8 + t]);
                bf[nt][1] = __float_as_uint(Bs[s][(n + g) * 20 + ks*8 + t + 4]);
            }
            #pragma unroll
            for (int mt = 0; mt < 4; mt++)
                #pragma unroll
                for (int nt = 0; nt < 4; nt++)
                    asm volatile(
                        "mma.sync.aligned.m16n8k8.row.col.f32.tf32.tf32.f32 "
                        "{%0,%1,%2,%3}, {%4,%5,%6,%7}, {%8,%9}, {%0,%1,%2,%3};"
                        : "+f"(acc[mt][nt][0]), "+f"(acc[mt][nt][1]),
                          "+f"(acc[mt][nt][2]), "+f"(acc[mt][nt][3])
                        : "r"(af[mt][0]), "r"(af[mt][1]), "r"(af[mt][2]), "r"(af[mt][3]),
                          "r"(bf[nt][0]), "r"(bf[nt][1]));
        }
        if (kt + 1 < NKT) {
            sstore((kt + 1) & 1);
            __syncthreads();
        }
    }

    // Epilogue: c0,c1 at (g, t*2..), c2,c3 at (g+8, t*2..)
    #pragma unroll
    for (int mt = 0; mt < 4; mt++) {
        int r0 = m0 + wm + mt * 16 + g;
        #pragma unroll
        for (int nt = 0; nt < 4; nt++) {
            int cn = n0 + wn + nt * 8 + t * 2;
            float2 bb = *(const float2*)(bias + cn);
            float2 o0 = { acc[mt][nt][0] + bb.x, acc[mt][nt][1] + bb.y };
            float2 o1 = { acc[mt][nt][2] + bb.x, acc[mt][nt][3] + bb.y };
            if (ADD_RES) {
                float2 ra = *(const float2*)(res + (size_t)r0 * DM + cn);
                float2 rb = *(const float2*)(res + (size_t)(r0 + 8) * DM + cn);
                o0.x += ra.x; o0.y += ra.y; o1.x += rb.x; o1.y += rb.y;
            }
            *(float2*)(C + (size_t)r0 * DM + cn) = o0;
            *(float2*)(C + (size_t)(r0 + 8) * DM + cn) = o1;
        }
    }
}

// ---------------------------------------------------------------------------
// SSM scan: one warp per (b,d), 2 states/lane, 32-step batches with
// multi-value butterfly reduce (31 shfl / 32 outputs, coalesced stores).
// Output transposed: ysT[d][b*SEQ + t].
// ---------------------------------------------------------------------------
__global__ void scan_kernel(const float* __restrict__ u,
                            const float* __restrict__ log_A,
                            const float* __restrict__ B_p,
                            const float* __restrict__ C_p,
                            const float* __restrict__ D_p,
                            const float* __restrict__ log_dt,
                            float* __restrict__ ysT) {
    int warp = (blockIdx.x * blockDim.x + threadIdx.x) >> 5;
    int lane = threadIdx.x & 31;
    if (warp >= BATCH * DM) return;
    int b = warp / DM, d = warp % DM;
    int n0 = lane * 2;

    float dt  = expf(log_dt[d]);
    float Ab0 = expf(dt * (-expf(log_A[d * NS + n0])));
    float Ab1 = expf(dt * (-expf(log_A[d * NS + n0 + 1])));
    float Bb0 = B_p[d * NS + n0]     * dt;
    float Bb1 = B_p[d * NS + n0 + 1] * dt;
    float C0  = C_p[d * NS + n0];
    float C1  = C_p[d * NS + n0 + 1];
    float Dd  = (lane == 0) ? D_p[d] : 0.f;   // D-term added exactly once

    const float* up = u + (size_t)b * SEQ * DM + d;
    float* yT = ysT + (size_t)d * MROWS + (size_t)b * SEQ;

    float h0 = 0.f, h1 = 0.f;
    for (int t0 = 0; t0 < SEQ; t0 += 32) {
        float p[32];
        #pragma unroll
        for (int i = 0; i < 32; i++) {
            float ut = __ldg(up + (size_t)(t0 + i) * DM);
            h0 = fmaf(Ab0, h0, Bb0 * ut);
            h1 = fmaf(Ab1, h1, Bb1 * ut);
            p[i] = fmaf(C0, h0, fmaf(C1, h1, Dd * ut));
        }
        // multi-value butterfly: after all levels, p[0] on lane L = out[t0+L]
        #pragma unroll
        for (int o = 16; o; o >>= 1) {
            bool hi = (lane & o) != 0;
            #pragma unroll
            for (int i = 0; i < o; i++) {
                float send = hi ? p[i] : p[i + o];
                float recv = __shfl_xor_sync(0xffffffffu, send, o);
                float keep = hi ? p[i + o] : p[i];
                p[i] = keep + recv;
            }
        }
        yT[t0 + lane] = p[0];
    }
}

// ---------------------------------------------------------------------------
extern "C" void kernel_launch(void* const* d_in, const int* in_sizes, int n_in,
                              void* d_out, int out_size) {
    const float* x        = (const float*)d_in[0];
    const float* ln_gamma = (const float*)d_in[1];
    const float* ln_beta  = (const float*)d_in[2];
    const float* W_in     = (const float*)d_in[3];
    const float* b_in     = (const float*)d_in[4];
    const float* log_A    = (const float*)d_in[5];
    const float* B_p      = (const float*)d_in[6];
    const float* C_p      = (const float*)d_in[7];
    const float* D_p      = (const float*)d_in[8];
    const float* log_dt   = (const float*)d_in[9];
    const float* W_out    = (const float*)d_in[10];
    const float* b_out    = (const float*)d_in[11];
    float* out = (float*)d_out;

    float *xn, *u, *ysT;
    cudaGetSymbolAddress((void**)&xn,  g_xn);
    cudaGetSymbolAddress((void**)&u,   g_u);
    cudaGetSymbolAddress((void**)&ysT, g_ysT);

    ln_kernel<<<MROWS / 8, 256>>>(x, ln_gamma, ln_beta, xn);

    dim3 g1(DM / 128, MROWS / 128);   // (6, 32)
    gemm_mma<false, false><<<g1, 256>>>(xn, W_in, b_in, nullptr, u);

    scan_kernel<<<(BATCH * DM * 32) / 128, 128>>>(u, log_A, B_p, C_p, D_p, log_dt, ysT);

    gemm_mma<true, true><<<g1, 256>>>(ysT, W_out, b_out, x, out);
}